// round 5
// baseline (speedup 1.0000x reference)
#include <cuda_runtime.h>
#include <cstdint>

typedef unsigned long long ull;
typedef unsigned int uint;

// Problem constants
#define BB   4
#define CC   128
#define HH   96
#define WW   96
#define OC   18          // G*K*K*2
#define HWP  (HH*WW)     // 9216
#define NPIX (BB*HWP)    // 36864

// ---------------- scratch (static device arrays; no allocation) ----------------
__device__ float4 g_cf2a[9 * NPIX];   // per (tap,pix): {c00,c00,c01,c01} pre-dup'd
__device__ float4 g_cf2b[9 * NPIX];   // per (tap,pix): {c10,c10,c11,c11}
__device__ uint   g_idx[9 * NPIX];    // packed 4x 4-bit gather indices (byte lanes)
__device__ float2 g_xt[(size_t)BB * HWP * 64];  // NHWC ch-paired: [b][h][w][cp]=(x[cp],x[cp+64])

// ---------------- f32x2 helpers ----------------
__device__ __forceinline__ void unpackf2(ull v, float& a, float& b) {
    asm("mov.b64 {%0, %1}, %2;" : "=f"(a), "=f"(b) : "l"(v));
}
__device__ __forceinline__ void fma2(ull& d, ull a, ull b) {
    asm("fma.rn.f32x2 %0, %1, %2, %0;" : "+l"(d) : "l"(a), "l"(b));
}
__device__ __forceinline__ ull mul2(ull a, ull b) {
    ull r; asm("mul.rn.f32x2 %0, %1, %2;" : "=l"(r) : "l"(a), "l"(b)); return r;
}
__device__ __forceinline__ ull add2(ull a, ull b) {
    ull r; asm("add.rn.f32x2 %0, %1, %2;" : "=l"(r) : "l"(a), "l"(b)); return r;
}
__device__ __forceinline__ uint f2tf32(float v) {
    uint r; asm("cvt.rna.tf32.f32 %0, %1;" : "=r"(r) : "f"(v)); return r;
}
__device__ __forceinline__ void mma_tf32(float* d, uint a0, uint a1, uint a2, uint a3,
                                         uint b0, uint b1) {
    asm("mma.sync.aligned.m16n8k8.row.col.f32.tf32.tf32.f32 "
        "{%0,%1,%2,%3},{%4,%5,%6,%7},{%8,%9},{%0,%1,%2,%3};"
        : "+f"(d[0]), "+f"(d[1]), "+f"(d[2]), "+f"(d[3])
        : "r"(a0), "r"(a1), "r"(a2), "r"(a3), "r"(b0), "r"(b1));
}

#define CONV_BLOCKS 96      // 4 batches x 24 row-quads
#define XS_CSTRIDE  600     // per-channel plane stride (uints); 600%32=24 -> conflict-free frags
#define XS_RSTRIDE  100

// ============================================================================
// Fused kernel A: tf32-mma conv (blocks 0..95) + transpose (blocks 96..1247).
//
// CONV as GEMM: D[384 pix, 24 out] += A[pix, k] * B[k, out], K = 128ch x 9taps.
//  Block covers 4 image rows (384 px) of one batch. 8 warps x 3 m16-tiles.
//  K grouped 8 channels at a time, ordered tap-major: k-step kk <-> tap kk,
//  k-lane <-> channel 0..7. A-frags: 4 conflict-free LDS.32 from padded x tile;
//  B-frags: 6 conflict-free LDS.32 from a 9x8x24 weight tile (cols 18..23 = 0).
//  Epilogue: mma accumulators (row=pixel, col pair=(ch,cw) of tap nt*4+tg)
//  -> clip/floor/bilinear coefs + packed ids, written pre-duplicated.
//
// TRANSPOSE: x NCHW -> NHWC channel-paired float2, overlapped with conv.
// ============================================================================
__global__ __launch_bounds__(256, 2)
void fusedA_kernel(const float* __restrict__ x, const float* __restrict__ rw,
                   const float* __restrict__ rb)
{
    __shared__ union {
        struct {
            uint xs[8 * XS_CSTRIDE];  // 8 ch x (6 rows x 98 cols, padded)
            uint ws[9 * 8 * 24];      // [tap][ch-lane][out]
        } cv;
        float2 tr[64][33];
    } sm;

    const int tid = threadIdx.x;
    const int bi  = blockIdx.x;

    if (bi >= CONV_BLOCKS) {
        // -------------------- TRANSPOSE role --------------------
        const int ti = bi - CONV_BLOCKS;             // 0..1151 = 3 x 96 x 4
        const int w0 = (ti % 3) * 32;
        const int h  = (ti / 3) % 96;
        const int b  = ti / 288;
        const int tx = tid & 31, ty = tid >> 5;      // ty 0..7

        const float* xb = x + ((size_t)b * CC) * HWP + h * WW + w0;
        #pragma unroll
        for (int k = 0; k < 8; k++) {
            int c = ty + 8 * k;                      // 0..63
            float v0 = xb[(size_t)c * HWP + tx];
            float v1 = xb[(size_t)(c + 64) * HWP + tx];
            sm.tr[c][tx] = make_float2(v0, v1);
        }
        __syncthreads();
        float2* ob = g_xt + ((size_t)(b * HH + h) * WW + w0) * 64;
        #pragma unroll
        for (int k = 0; k < 8; k++) {
            int cp = tx + 32 * (k & 1);
            int wl = ty + 8 * (k >> 1);
            ob[(size_t)wl * 64 + cp] = sm.tr[cp][wl];
        }
        return;
    }

    // -------------------- CONV role --------------------
    const int lane = tid & 31;
    const int warp = tid >> 5;        // 0..7
    const int g  = lane >> 2;         // groupID 0..7
    const int tg = lane & 3;          // threadID-in-group 0..3

    const int b  = bi / 24;
    const int h0 = (bi % 24) * 4;     // 4 image rows per block

    float D[3][3][4];
    #pragma unroll
    for (int i = 0; i < 3; i++)
        #pragma unroll
        for (int j = 0; j < 3; j++)
            #pragma unroll
            for (int k = 0; k < 4; k++) D[i][j][k] = 0.0f;

    for (int cg = 0; cg < 16; cg++) {
        __syncthreads();
        // stage x: 8 ch x 6 rows (h0-1..h0+4) x 98 cols (img -1..96), tf32
        {
            const float* xg = x + ((size_t)(b * CC + cg * 8)) * HWP;
            for (int i = tid; i < 8 * 588; i += 256) {
                int cl = i / 588, rem = i - cl * 588;
                int rr = rem / 98, cc = rem - rr * 98;
                int grow = h0 - 1 + rr, gcol = cc - 1;
                float v = 0.0f;
                if ((unsigned)grow < (unsigned)HH && (unsigned)gcol < (unsigned)WW)
                    v = xg[(size_t)cl * HWP + grow * WW + gcol];
                sm.cv.xs[cl * XS_CSTRIDE + rr * XS_RSTRIDE + cc] = f2tf32(v);
            }
        }
        // stage w: ws[t][cl][o] (o>=18 zero), tf32
        for (int i = tid; i < 1728; i += 256) {
            int t = i / 192, rem = i - t * 192;
            int cl = rem / 24, o = rem - cl * 24;
            float v = (o < OC) ? rw[((size_t)o * CC + cg * 8 + cl) * 9 + t] : 0.0f;
            sm.cv.ws[i] = f2tf32(v);
        }
        __syncthreads();

        #pragma unroll
        for (int kk = 0; kk < 9; kk++) {          // tap = kk
            const int dr = kk / 3, dc = kk % 3;
            uint b0[3], b1[3];
            #pragma unroll
            for (int nt = 0; nt < 3; nt++) {
                b0[nt] = sm.cv.ws[kk * 192 + tg * 24 + nt * 8 + g];
                b1[nt] = sm.cv.ws[kk * 192 + (tg + 4) * 24 + nt * 8 + g];
            }
            #pragma unroll
            for (int mt = 0; mt < 3; mt++) {
                const int m  = warp + mt * 8;      // m16-tile 0..23
                const int r  = m / 6;              // row 0..3 within block
                const int cb = (m % 6) * 16;       // col base
                const int base = (r + dr) * XS_RSTRIDE + cb + dc + g;
                uint a0 = sm.cv.xs[tg * XS_CSTRIDE + base];
                uint a1 = sm.cv.xs[tg * XS_CSTRIDE + base + 8];
                uint a2 = sm.cv.xs[(tg + 4) * XS_CSTRIDE + base];
                uint a3 = sm.cv.xs[(tg + 4) * XS_CSTRIDE + base + 8];
                #pragma unroll
                for (int nt = 0; nt < 3; nt++)
                    mma_tf32(D[mt][nt], a0, a1, a2, a3, b0[nt], b1[nt]);
            }
        }
    }

    // ---- epilogue: accumulators -> bilinear coefs + ids ----
    #pragma unroll
    for (int mt = 0; mt < 3; mt++) {
        const int m  = warp + mt * 8;
        const int r  = m / 6;
        const int cb = (m % 6) * 16;
        const int pixbase = b * HWP + (h0 + r) * WW + cb + g;
        #pragma unroll
        for (int nt = 0; nt < 3; nt++) {
            const int t = nt * 4 + tg;
            if (t > 8) continue;
            const float bh = __ldg(rb + 2 * t)     + 0.5f + (float)(t / 3);
            const float bw = __ldg(rb + 2 * t + 1) + 0.5f + (float)(t % 3);
            #pragma unroll
            for (int half = 0; half < 2; half++) {
                const int pix = pixbase + half * 8;
                float chv = D[mt][nt][2 * half]     + bh;
                float cwv = D[mt][nt][2 * half + 1] + bw;
                chv = fminf(fmaxf(chv, 0.0f), 3.0f);
                cwv = fminf(fmaxf(cwv, 0.0f), 3.0f);
                float h0f = floorf(chv), w0f = floorf(cwv);
                float lh = chv - h0f, lw = cwv - w0f;
                int h0i = (int)h0f, w0i = (int)w0f;
                int h1i = min(h0i + 1, 3), w1i = min(w0i + 1, 3);
                float c00 = (1.0f - lh) * (1.0f - lw);
                float c01 = (1.0f - lh) * lw;
                float c10 = lh * (1.0f - lw);
                float c11 = lh * lw;
                const size_t gidx = (size_t)t * NPIX + pix;
                g_cf2a[gidx] = make_float4(c00, c00, c01, c01);
                g_cf2b[gidx] = make_float4(c10, c10, c11, c11);
                g_idx[gidx]  = (uint)(h0i * 4 + w0i)
                             | ((uint)(h0i * 4 + w1i) << 8)
                             | ((uint)(h1i * 4 + w0i) << 16)
                             | ((uint)(h1i * 4 + w1i) << 24);
            }
        }
    }
}

// ============================================================================
// Kernel 2: deform gather, coalesced output. Coefs now preloaded (pre-dup'd).
// Block = 256 threads: cp(64) x pg(4). Tile = 1 row x 32 px x 128 ch.
// ============================================================================
__global__ __launch_bounds__(256)
void deform_kernel(const float* __restrict__ wt, float* __restrict__ out)
{
    __shared__ float2 wt2[16][64];
    __shared__ float4 cfa[9][32];
    __shared__ float4 cfb[9][32];
    __shared__ uint   ids[9][32];
    __shared__ float  resL[64][33];
    __shared__ float  resH[64][33];

    const int tid = threadIdx.x;
    const int cp = tid & 63;            // channel pair lane
    const int pg = tid >> 6;            // pixel group 0..3 -> pixels 8pg..8pg+7
    const int w0 = blockIdx.x * 32;
    const int h  = blockIdx.y;
    const int b  = blockIdx.z;
    const int px0 = pg * 8;

    // stage channel-paired weight table
    for (int i = tid; i < 16 * 64; i += 256) {
        int s = i >> 6, c = i & 63;
        wt2[s][c] = make_float2(wt[c * 16 + s], wt[(c + 64) * 16 + s]);
    }
    // stage coefs + ids for the 32-pixel row segment
    {
        const int pixbase = b * HWP + h * WW + w0;
        for (int i = tid; i < 288; i += 256) {
            int t = i >> 5, p = i & 31;
            size_t gx = (size_t)t * NPIX + pixbase + p;
            cfa[t][p] = g_cf2a[gx];
            cfb[t][p] = g_cf2b[gx];
            ids[t][p] = g_idx[gx];
        }
    }
    __syncthreads();

    const float2* xt = g_xt + (size_t)b * HWP * 64 + cp;
    const bool rok0 = (h >= 1), rok2 = (h <= HH - 2);

    ull xv[3][4];
    #pragma unroll
    for (int dj = 0; dj < 2; dj++) {
        int gc = w0 + px0 - 1 + dj;
        bool cok = (unsigned)gc < (unsigned)WW;
        #pragma unroll
        for (int di = 0; di < 3; di++) {
            bool ok = cok && ((di == 0) ? rok0 : (di == 2) ? rok2 : true);
            ull v = 0ull;
            if (ok) v = *(const ull*)(xt + ((size_t)(h + di - 1) * WW + gc) * 64);
            xv[di][dj] = v;
        }
    }

    #pragma unroll
    for (int pp = 0; pp < 4; pp++) {
        const int p0 = px0 + 2 * pp;
        #pragma unroll
        for (int dj = 2; dj < 4; dj++) {
            int gc = w0 + p0 - 1 + dj;
            bool cok = gc < WW;
            #pragma unroll
            for (int di = 0; di < 3; di++) {
                bool ok = cok && ((di == 0) ? rok0 : (di == 2) ? rok2 : true);
                ull v = 0ull;
                if (ok) v = *(const ull*)(xt + ((size_t)(h + di - 1) * WW + gc) * 64);
                xv[di][dj] = v;
            }
        }

        ull accA0 = 0ull, accA1 = 0ull, accB0 = 0ull, accB1 = 0ull;
        #pragma unroll
        for (int t = 0; t < 9; t++) {
            const int tr = t / 3, tc = t % 3;
            { // pixel A
                const ulonglong2 ca = *(const ulonglong2*)&cfa[t][p0];
                const ulonglong2 cb = *(const ulonglong2*)&cfb[t][p0];
                const uint ox = ids[t][p0];
                ull g00 = *(const ull*)&wt2[ ox        & 15u][cp];
                ull g01 = *(const ull*)&wt2[(ox >> 8)  & 15u][cp];
                ull g10 = *(const ull*)&wt2[(ox >> 16) & 15u][cp];
                ull g11 = *(const ull*)&wt2[(ox >> 24) & 15u][cp];
                ull s0 = mul2(ca.x, g00); fma2(s0, ca.y, g01);
                ull s1 = mul2(cb.x, g10); fma2(s1, cb.y, g11);
                fma2(accA0, s0, xv[tr][tc]);
                fma2(accA1, s1, xv[tr][tc]);
            }
            { // pixel B
                const ulonglong2 ca = *(const ulonglong2*)&cfa[t][p0 + 1];
                const ulonglong2 cb = *(const ulonglong2*)&cfb[t][p0 + 1];
                const uint ox = ids[t][p0 + 1];
                ull g00 = *(const ull*)&wt2[ ox        & 15u][cp];
                ull g01 = *(const ull*)&wt2[(ox >> 8)  & 15u][cp];
                ull g10 = *(const ull*)&wt2[(ox >> 16) & 15u][cp];
                ull g11 = *(const ull*)&wt2[(ox >> 24) & 15u][cp];
                ull s0 = mul2(ca.x, g00); fma2(s0, ca.y, g01);
                ull s1 = mul2(cb.x, g10); fma2(s1, cb.y, g11);
                fma2(accB0, s0, xv[tr][tc + 1]);
                fma2(accB1, s1, xv[tr][tc + 1]);
            }
        }

        float aL, aH, bL, bH;
        unpackf2(add2(accA0, accA1), aL, aH);
        unpackf2(add2(accB0, accB1), bL, bH);
        resL[cp][p0]     = aL; resH[cp][p0]     = aH;
        resL[cp][p0 + 1] = bL; resH[cp][p0 + 1] = bH;

        #pragma unroll
        for (int di = 0; di < 3; di++) { xv[di][0] = xv[di][2]; xv[di][1] = xv[di][3]; }
    }
    __syncthreads();

    // coalesced NCHW write: 128 ch x 32 px
    float* ob = out + (size_t)b * CC * HWP + h * WW + w0;
    #pragma unroll
    for (int i = tid; i < 128 * 32; i += 256) {
        int c = i >> 5, p = i & 31;
        float v = (c < 64) ? resL[c][p] : resH[c - 64][p];
        ob[(size_t)c * HWP + p] = v;
    }
}

// ============================================================================
extern "C" void kernel_launch(void* const* d_in, const int* in_sizes, int n_in,
                              void* d_out, int out_size)
{
    const float* x  = (const float*)d_in[0];   // [4,128,96,96]
    const float* rw = (const float*)d_in[1];   // [18,128,3,3]
    const float* rb = (const float*)d_in[2];   // [18]
    const float* wt = (const float*)d_in[3];   // [128,4,4]
    float* out = (float*)d_out;                // [4,128,96,96]

    fusedA_kernel<<<CONV_BLOCKS + 1152, 256>>>(x, rw, rb);
    deform_kernel<<<dim3(3, HH, BB), 256>>>(wt, out);
}

// round 6
// speedup vs baseline: 1.3722x; 1.3722x over previous
#include <cuda_runtime.h>
#include <cstdint>

typedef unsigned long long ull;
typedef unsigned int uint;

// Problem constants
#define BB   4
#define CC   128
#define HH   96
#define WW   96
#define OC   18          // G*K*K*2
#define HWP  (HH*WW)     // 9216
#define NPIX (BB*HWP)    // 36864
#define KCH  8           // split-K chunks for conv (each = 2 channel-groups of 8)

// ---------------- scratch (static device arrays; no allocation) ----------------
__device__ float  g_rotp[KCH * BB * OC * HWP];        // conv partial coord sums
__device__ float2 g_xt[(size_t)BB * HWP * 64];        // NHWC ch-paired: [b][h][w][cp]

// ---------------- f32x2 helpers ----------------
__device__ __forceinline__ void unpackf2(ull v, float& a, float& b) {
    asm("mov.b64 {%0, %1}, %2;" : "=f"(a), "=f"(b) : "l"(v));
}
__device__ __forceinline__ void fma2(ull& d, ull a, ull b) {
    asm("fma.rn.f32x2 %0, %1, %2, %0;" : "+l"(d) : "l"(a), "l"(b));
}
__device__ __forceinline__ ull mul2(ull a, ull b) {
    ull r; asm("mul.rn.f32x2 %0, %1, %2;" : "=l"(r) : "l"(a), "l"(b)); return r;
}
__device__ __forceinline__ ull add2(ull a, ull b) {
    ull r; asm("add.rn.f32x2 %0, %1, %2;" : "=l"(r) : "l"(a), "l"(b)); return r;
}
__device__ __forceinline__ uint f2tf32(float v) {
    uint r; asm("cvt.rna.tf32.f32 %0, %1;" : "=r"(r) : "f"(v)); return r;
}
__device__ __forceinline__ void mma_tf32(float* d, uint a0, uint a1, uint a2, uint a3,
                                         uint b0, uint b1) {
    asm("mma.sync.aligned.m16n8k8.row.col.f32.tf32.tf32.f32 "
        "{%0,%1,%2,%3},{%4,%5,%6,%7},{%8,%9},{%0,%1,%2,%3};"
        : "+f"(d[0]), "+f"(d[1]), "+f"(d[2]), "+f"(d[3])
        : "r"(a0), "r"(a1), "r"(a2), "r"(a3), "r"(b0), "r"(b1));
}

#define CONV_BLOCKS (BB * 24 * KCH)   // 768
#define XS_CSTRIDE  600               // per-channel plane stride (uints); %32=24 -> conflict-free
#define XS_RSTRIDE  100

// ============================================================================
// Fused kernel A: tf32-mma conv split-K (blocks 0..767) + transpose (768..1919).
//
// CONV as GEMM: D[384 pix, 24 out] += A[pix,k]*B[k,out]; this block sums only
//  channels [chunk*16, chunk*16+16) (2 channel-groups of 8), K-order tap-major.
//  Epilogue writes RAW coordinate partial sums to g_rotp[chunk].
// TRANSPOSE: x NCHW -> NHWC channel-paired float2, overlapped with conv.
// ============================================================================
__global__ __launch_bounds__(256, 2)
void fusedA_kernel(const float* __restrict__ x, const float* __restrict__ rw)
{
    __shared__ union {
        struct {
            uint xs[8 * XS_CSTRIDE];  // 8 ch x (6 rows x 98 cols, padded)
            uint ws[9 * 8 * 24];      // [tap][ch-lane][out]
        } cv;
        float2 tr[64][33];
    } sm;

    const int tid = threadIdx.x;
    const int bi  = blockIdx.x;

    if (bi >= CONV_BLOCKS) {
        // -------------------- TRANSPOSE role --------------------
        const int ti = bi - CONV_BLOCKS;             // 0..1151 = 3 x 96 x 4
        const int w0 = (ti % 3) * 32;
        const int h  = (ti / 3) % 96;
        const int b  = ti / 288;
        const int tx = tid & 31, ty = tid >> 5;      // ty 0..7

        const float* xb = x + ((size_t)b * CC) * HWP + h * WW + w0;
        #pragma unroll
        for (int k = 0; k < 8; k++) {
            int c = ty + 8 * k;                      // 0..63
            float v0 = xb[(size_t)c * HWP + tx];
            float v1 = xb[(size_t)(c + 64) * HWP + tx];
            sm.tr[c][tx] = make_float2(v0, v1);
        }
        __syncthreads();
        float2* ob = g_xt + ((size_t)(b * HH + h) * WW + w0) * 64;
        #pragma unroll
        for (int k = 0; k < 8; k++) {
            int cp = tx + 32 * (k & 1);
            int wl = ty + 8 * (k >> 1);
            ob[(size_t)wl * 64 + cp] = sm.tr[cp][wl];
        }
        return;
    }

    // -------------------- CONV role --------------------
    const int lane = tid & 31;
    const int warp = tid >> 5;        // 0..7
    const int g  = lane >> 2;         // groupID 0..7
    const int tg = lane & 3;          // threadID-in-group 0..3

    const int b     = bi / (24 * KCH);
    const int rest  = bi % (24 * KCH);
    const int h0    = (rest % 24) * 4;     // 4 image rows per block
    const int chunk = rest / 24;           // 0..7

    float D[3][3][4];
    #pragma unroll
    for (int i = 0; i < 3; i++)
        #pragma unroll
        for (int j = 0; j < 3; j++)
            #pragma unroll
            for (int k = 0; k < 4; k++) D[i][j][k] = 0.0f;

    #pragma unroll 1
    for (int s = 0; s < 2; s++) {
        const int cg = chunk * 2 + s;     // channel-group of 8
        __syncthreads();
        // stage x: 8 ch x 6 rows (h0-1..h0+4) x 98 cols (img -1..96), tf32
        {
            const float* xg = x + ((size_t)(b * CC + cg * 8)) * HWP;
            for (int i = tid; i < 8 * 588; i += 256) {
                int cl = i / 588, rem = i - cl * 588;
                int rr = rem / 98, cc = rem - rr * 98;
                int grow = h0 - 1 + rr, gcol = cc - 1;
                float v = 0.0f;
                if ((unsigned)grow < (unsigned)HH && (unsigned)gcol < (unsigned)WW)
                    v = xg[(size_t)cl * HWP + grow * WW + gcol];
                sm.cv.xs[cl * XS_CSTRIDE + rr * XS_RSTRIDE + cc] = f2tf32(v);
            }
        }
        // stage w: ws[t][cl][o] (o>=18 zero), tf32
        for (int i = tid; i < 1728; i += 256) {
            int t = i / 192, rem = i - t * 192;
            int cl = rem / 24, o = rem - cl * 24;
            float v = (o < OC) ? rw[((size_t)o * CC + cg * 8 + cl) * 9 + t] : 0.0f;
            sm.cv.ws[i] = f2tf32(v);
        }
        __syncthreads();

        #pragma unroll
        for (int kk = 0; kk < 9; kk++) {          // tap = kk
            const int dr = kk / 3, dc = kk % 3;
            uint b0[3], b1[3];
            #pragma unroll
            for (int nt = 0; nt < 3; nt++) {
                b0[nt] = sm.cv.ws[kk * 192 + tg * 24 + nt * 8 + g];
                b1[nt] = sm.cv.ws[kk * 192 + (tg + 4) * 24 + nt * 8 + g];
            }
            #pragma unroll
            for (int mt = 0; mt < 3; mt++) {
                const int m  = warp + mt * 8;      // m16-tile 0..23
                const int r  = m / 6;              // row 0..3 within block
                const int cb = (m % 6) * 16;       // col base
                const int base = (r + dr) * XS_RSTRIDE + cb + dc + g;
                uint a0 = sm.cv.xs[tg * XS_CSTRIDE + base];
                uint a1 = sm.cv.xs[tg * XS_CSTRIDE + base + 8];
                uint a2 = sm.cv.xs[(tg + 4) * XS_CSTRIDE + base];
                uint a3 = sm.cv.xs[(tg + 4) * XS_CSTRIDE + base + 8];
                #pragma unroll
                for (int nt = 0; nt < 3; nt++)
                    mma_tf32(D[mt][nt], a0, a1, a2, a3, b0[nt], b1[nt]);
            }
        }
    }

    // ---- epilogue: write raw coordinate partial sums ----
    float* rp = g_rotp + (size_t)(chunk * BB + b) * OC * HWP;
    #pragma unroll
    for (int mt = 0; mt < 3; mt++) {
        const int m  = warp + mt * 8;
        const int r  = m / 6;
        const int cb = (m % 6) * 16;
        const int pl = (h0 + r) * WW + cb + g;     // pixel offset within image
        #pragma unroll
        for (int nt = 0; nt < 3; nt++) {
            const int t = nt * 4 + tg;
            if (t > 8) continue;
            #pragma unroll
            for (int half = 0; half < 2; half++) {
                rp[(size_t)(2 * t)     * HWP + pl + half * 8] = D[mt][nt][2 * half];
                rp[(size_t)(2 * t + 1) * HWP + pl + half * 8] = D[mt][nt][2 * half + 1];
            }
        }
    }
}

// ============================================================================
// Kernel 2: fused coef + deform gather, coalesced output.
// Prologue computes bilinear coefs from 8 rotp partials, stores PRE-DUP'd in
// smem (inner-loop dup-MOVs replaced by broadcast LDS.128 -> near-free).
// Block = 256 threads: cp(64) x pg(4). Tile = 1 row x 32 px x 128 ch.
// ============================================================================
__global__ __launch_bounds__(256)
void deform_kernel(const float* __restrict__ wt, const float* __restrict__ rb,
                   float* __restrict__ out)
{
    __shared__ float2 wt2[16][64];
    __shared__ float4 cfa[9][32];    // {c00,c00,c01,c01}
    __shared__ float4 cfb[9][32];    // {c10,c10,c11,c11}
    __shared__ uint   ids[9][32];
    __shared__ float  resL[64][33];
    __shared__ float  resH[64][33];

    const int tid = threadIdx.x;
    const int cp = tid & 63;            // channel pair lane
    const int pg = tid >> 6;            // pixel group 0..3 -> pixels 8pg..8pg+7
    const int w0 = blockIdx.x * 32;
    const int h  = blockIdx.y;
    const int b  = blockIdx.z;
    const int px0 = pg * 8;

    // stage channel-paired weight table
    for (int i = tid; i < 16 * 64; i += 256) {
        int s = i >> 6, c = i & 63;
        wt2[s][c] = make_float2(wt[c * 16 + s], wt[(c + 64) * 16 + s]);
    }

    // fused coef: items (t 0..8, p 0..31) = 288 ; sum KCH partials + bias
    for (int i = tid; i < 288; i += 256) {
        int t = i >> 5, p = i & 31;
        int off = h * WW + w0 + p;
        int o0 = 2 * t, o1 = 2 * t + 1;
        float chv = rb[o0] + 0.5f + (float)(t / 3);
        float cwv = rb[o1] + 0.5f + (float)(t % 3);
        #pragma unroll
        for (int ch = 0; ch < KCH; ch++) {
            const float* base = g_rotp + ((size_t)(ch * BB + b) * OC) * HWP + off;
            chv += base[(size_t)o0 * HWP];
            cwv += base[(size_t)o1 * HWP];
        }
        chv = fminf(fmaxf(chv, 0.0f), 3.0f);
        cwv = fminf(fmaxf(cwv, 0.0f), 3.0f);
        float h0f = floorf(chv), w0f = floorf(cwv);
        float lh = chv - h0f, lw = cwv - w0f;
        int h0i = (int)h0f, w0i = (int)w0f;
        int h1i = min(h0i + 1, 3), w1i = min(w0i + 1, 3);
        float c00 = (1.0f - lh) * (1.0f - lw);
        float c01 = (1.0f - lh) * lw;
        float c10 = lh * (1.0f - lw);
        float c11 = lh * lw;
        cfa[t][p] = make_float4(c00, c00, c01, c01);
        cfb[t][p] = make_float4(c10, c10, c11, c11);
        ids[t][p] = (uint)(h0i * 4 + w0i)
                  | ((uint)(h0i * 4 + w1i) << 8)
                  | ((uint)(h1i * 4 + w0i) << 16)
                  | ((uint)(h1i * 4 + w1i) << 24);
    }
    __syncthreads();

    const float2* xt = g_xt + (size_t)b * HWP * 64 + cp;
    const bool rok0 = (h >= 1), rok2 = (h <= HH - 2);

    ull xv[3][4];
    #pragma unroll
    for (int dj = 0; dj < 2; dj++) {
        int gc = w0 + px0 - 1 + dj;
        bool cok = (unsigned)gc < (unsigned)WW;
        #pragma unroll
        for (int di = 0; di < 3; di++) {
            bool ok = cok && ((di == 0) ? rok0 : (di == 2) ? rok2 : true);
            ull v = 0ull;
            if (ok) v = *(const ull*)(xt + ((size_t)(h + di - 1) * WW + gc) * 64);
            xv[di][dj] = v;
        }
    }

    #pragma unroll
    for (int pp = 0; pp < 4; pp++) {
        const int p0 = px0 + 2 * pp;
        #pragma unroll
        for (int dj = 2; dj < 4; dj++) {
            int gc = w0 + p0 - 1 + dj;
            bool cok = gc < WW;
            #pragma unroll
            for (int di = 0; di < 3; di++) {
                bool ok = cok && ((di == 0) ? rok0 : (di == 2) ? rok2 : true);
                ull v = 0ull;
                if (ok) v = *(const ull*)(xt + ((size_t)(h + di - 1) * WW + gc) * 64);
                xv[di][dj] = v;
            }
        }

        ull accA0 = 0ull, accA1 = 0ull, accB0 = 0ull, accB1 = 0ull;
        #pragma unroll
        for (int t = 0; t < 9; t++) {
            const int tr = t / 3, tc = t % 3;
            { // pixel A
                const ulonglong2 ca = *(const ulonglong2*)&cfa[t][p0];
                const ulonglong2 cb = *(const ulonglong2*)&cfb[t][p0];
                const uint ox = ids[t][p0];
                ull g00 = *(const ull*)&wt2[ ox        & 15u][cp];
                ull g01 = *(const ull*)&wt2[(ox >> 8)  & 15u][cp];
                ull g10 = *(const ull*)&wt2[(ox >> 16) & 15u][cp];
                ull g11 = *(const ull*)&wt2[(ox >> 24) & 15u][cp];
                ull s0 = mul2(ca.x, g00); fma2(s0, ca.y, g01);
                ull s1 = mul2(cb.x, g10); fma2(s1, cb.y, g11);
                fma2(accA0, s0, xv[tr][tc]);
                fma2(accA1, s1, xv[tr][tc]);
            }
            { // pixel B
                const ulonglong2 ca = *(const ulonglong2*)&cfa[t][p0 + 1];
                const ulonglong2 cb = *(const ulonglong2*)&cfb[t][p0 + 1];
                const uint ox = ids[t][p0 + 1];
                ull g00 = *(const ull*)&wt2[ ox        & 15u][cp];
                ull g01 = *(const ull*)&wt2[(ox >> 8)  & 15u][cp];
                ull g10 = *(const ull*)&wt2[(ox >> 16) & 15u][cp];
                ull g11 = *(const ull*)&wt2[(ox >> 24) & 15u][cp];
                ull s0 = mul2(ca.x, g00); fma2(s0, ca.y, g01);
                ull s1 = mul2(cb.x, g10); fma2(s1, cb.y, g11);
                fma2(accB0, s0, xv[tr][tc + 1]);
                fma2(accB1, s1, xv[tr][tc + 1]);
            }
        }

        float aL, aH, bL, bH;
        unpackf2(add2(accA0, accA1), aL, aH);
        unpackf2(add2(accB0, accB1), bL, bH);
        resL[cp][p0]     = aL; resH[cp][p0]     = aH;
        resL[cp][p0 + 1] = bL; resH[cp][p0 + 1] = bH;

        #pragma unroll
        for (int di = 0; di < 3; di++) { xv[di][0] = xv[di][2]; xv[di][1] = xv[di][3]; }
    }
    __syncthreads();

    // coalesced NCHW write: 128 ch x 32 px
    float* ob = out + (size_t)b * CC * HWP + h * WW + w0;
    #pragma unroll
    for (int i = tid; i < 128 * 32; i += 256) {
        int c = i >> 5, p = i & 31;
        float v = (c < 64) ? resL[c][p] : resH[c - 64][p];
        ob[(size_t)c * HWP + p] = v;
    }
}

// ============================================================================
extern "C" void kernel_launch(void* const* d_in, const int* in_sizes, int n_in,
                              void* d_out, int out_size)
{
    const float* x  = (const float*)d_in[0];   // [4,128,96,96]
    const float* rw = (const float*)d_in[1];   // [18,128,3,3]
    const float* rb = (const float*)d_in[2];   // [18]
    const float* wt = (const float*)d_in[3];   // [128,4,4]
    float* out = (float*)d_out;                // [4,128,96,96]

    fusedA_kernel<<<CONV_BLOCKS + 1152, 256>>>(x, rw);
    deform_kernel<<<dim3(3, HH, BB), 256>>>(wt, rb, out);
}